// round 11
// baseline (speedup 1.0000x reference)
#include <cuda_runtime.h>

// Problem constants (shapes fixed by the dataset)
#define B 16
#define F 256
#define T 8192
#define KKEEP 204                 // k = int(256 * (1 - 0.2))

#define N1 (B * F * T)            // 33,554,432 floats per output tensor
#define N4_MASKED (N1 / 4)        // 8,388,608 float4 (masked_x half)

// Single kernel, no inter-block deps:
//   masked: 8192 blocks x 1024 f4 (one half (b,f) row; warp-local mask calc)
//   bcast:  2048 blocks x 4096 f4 (write-only; smem mask-row prologue)
#define MASKED_BLOCKS 8192
#define MB_F4 1024
#define BCAST_BLOCKS 2048
#define BB_F4 4096

// kept(f) <=> #{j : x2[j] > x2[f]} < KKEEP   (tie-correct vs top_k kth value)
// binary  = kept && (x2 > 0)                 (probs > 0.5 <=> wta > 0)
__global__ void fused_kernel(const float* __restrict__ w_mask,
                             const float* __restrict__ noise,
                             const float4* __restrict__ x,
                             float4* __restrict__ out) {
    const int tid = threadIdx.x;                      // 256 threads

    if (blockIdx.x < MASKED_BLOCKS) {
        // ---- masked_x block: warp-local single-mask-value computation ----
        const int baseV = blockIdx.x * MB_F4;         // first f4 index
        const int b  = baseV >> 19;                   // F*T/4 f4 per batch
        const int f0 = (baseV >> 11) & (F - 1);       // this block's feature
        const int lane = tid & 31;

        // Each lane evaluates x2 for features {c*32 + lane}. All loads are
        // L1/L2 hits after the first touching block (16 KB working set).
        float x2v[8];
#pragma unroll
        for (int c = 0; c < 8; ++c) {
            const float w = __ldg(&w_mask[c * 32 + lane]);
            const float n = __ldg(&noise[b * F + c * 32 + lane]);
            x2v[c] = 1.0f / (1.0f + __expf(-w)) + 0.05f * n;
        }
        // Broadcast x2[f0] from its owning lane; count strictly-greater.
        const float x2f = __shfl_sync(0xffffffffu, x2v[f0 >> 5], f0 & 31);
        int g = 0;
#pragma unroll
        for (int c = 0; c < 8; ++c)
            g += __popc(__ballot_sync(0xffffffffu, x2v[c] > x2f));
        const float m = (g < KKEEP && x2f > 0.0f) ? 1.0f : 0.0f;

        if (m != 0.0f) {
            float4 xv[4];
#pragma unroll
            for (int k = 0; k < 4; ++k)               // front-batched (MLP=4)
                xv[k] = __ldcs(&x[baseV + k * 256 + tid]);
#pragma unroll
            for (int k = 0; k < 4; ++k)
                __stcs(&out[baseV + k * 256 + tid], xv[k]);
        } else {
            const float4 z = make_float4(0.f, 0.f, 0.f, 0.f);
#pragma unroll
            for (int k = 0; k < 4; ++k)               // row dropped: no reads
                __stcs(&out[baseV + k * 256 + tid], z);
        }
    } else {
        // ---- binary_mask block (write-only): smem mask-row prologue ----
        __shared__ __align__(16) float s[F];
        __shared__ __align__(16) float mask_s[F];     // read as float4
        const int w0 = (blockIdx.x - MASKED_BLOCKS) * BB_F4;
        const int b  = w0 >> 19;                      // T*F/4 f4 per batch
        const int baseV = N4_MASKED + w0;

        const float w  = __ldg(&w_mask[tid]);
        const float sg = 1.0f / (1.0f + __expf(-w));
        const float x2 = sg + 0.05f * __ldg(&noise[b * F + tid]);
        s[tid] = x2;
        __syncthreads();
        int gt = 0;
#pragma unroll 16
        for (int j = 0; j < F; ++j)
            gt += (s[j] > x2) ? 1 : 0;                // uniform-addr LDS: N=1
        mask_s[tid] = (gt < KKEEP && x2 > 0.0f) ? 1.0f : 0.0f;
        __syncthreads();

        // f4 lane = (w0 + it*256 + tid) & 63 = tid & 63 (w0,256 ≡ 0 mod 64)
        const float4 m4 = ((const float4*)mask_s)[tid & 63];
#pragma unroll 8
        for (int it = 0; it < 16; ++it)
            __stcs(&out[baseV + it * 256 + tid], m4);
    }
}

extern "C" void kernel_launch(void* const* d_in, const int* in_sizes, int n_in,
                              void* d_out, int out_size) {
    const float* x      = (const float*)d_in[0];   // (16,1,256,8192) f32
    const float* w_mask = (const float*)d_in[1];   // (1,1,1,256)     f32
    const float* noise  = (const float*)d_in[2];   // (16,1,1,256)    f32
    float* out = (float*)d_out;

    const bool has_bcast = ((long long)out_size >= 2LL * N1);
    const int blocks = MASKED_BLOCKS + (has_bcast ? BCAST_BLOCKS : 0);

    fused_kernel<<<blocks, 256>>>(w_mask, noise,
                                  (const float4*)x, (float4*)out);
}